// round 9
// baseline (speedup 1.0000x reference)
#include <cuda_runtime.h>
#include <cuda_bf16.h>
#include <cstdint>
#include <math.h>

#define B_ROWS 8192
#define D_DIM  4096
#define A_DIM  1024
#define H_DIM  128
#define C_DIM  16

// ---------------------------------------------------------------------------
// Scratch (module-scope device memory; no runtime allocation).
// ---------------------------------------------------------------------------
__device__ float g_A[(size_t)B_ROWS * D_DIM];            // 128 MB: attention logits
__device__ float g_H[B_ROWS * H_DIM];                    // 4 MB  : relu(weighted@Wc1+bc1)
__device__ __nv_bfloat16 g_Xhi[(size_t)B_ROWS * D_DIM];  // x-split, then weighted-split
__device__ __nv_bfloat16 g_Xlo[(size_t)B_ROWS * D_DIM];
__device__ __nv_bfloat16 g_Thi[B_ROWS * A_DIM];          // tanh(x@W1+b1) split
__device__ __nv_bfloat16 g_Tlo[B_ROWS * A_DIM];
__device__ __nv_bfloat16 g_W1t_hi[A_DIM * D_DIM];        // [N,K] = [1024,4096]
__device__ __nv_bfloat16 g_W1t_lo[A_DIM * D_DIM];
__device__ __nv_bfloat16 g_W2t_hi[D_DIM * A_DIM];        // [4096,1024]
__device__ __nv_bfloat16 g_W2t_lo[D_DIM * A_DIM];
__device__ __nv_bfloat16 g_Wc1t_hi[H_DIM * D_DIM];       // [128,4096]
__device__ __nv_bfloat16 g_Wc1t_lo[H_DIM * D_DIM];

// ---------------------------------------------------------------------------
// PTX helpers — baseline (non-'a') instructions only.
// ---------------------------------------------------------------------------
__device__ __forceinline__ uint32_t smem_to_u32(const void* p) {
    uint32_t a;
    asm("{ .reg .u64 t; cvta.to.shared.u64 t, %1; cvt.u32.u64 %0, t; }"
        : "=r"(a) : "l"(p));
    return a;
}

__device__ __forceinline__ void cp16(uint32_t saddr, const void* gaddr) {
    asm volatile("cp.async.cg.shared.global [%0], [%1], 16;"
                 :: "r"(saddr), "l"(gaddr));
}
#define CP_COMMIT()  asm volatile("cp.async.commit_group;" ::: "memory")
#define CP_WAIT(n)   asm volatile("cp.async.wait_group %0;" :: "n"(n) : "memory")

__device__ __forceinline__ void ldsm_x4(uint32_t* r, uint32_t addr) {
    asm volatile("ldmatrix.sync.aligned.m8n8.x4.shared.b16 {%0,%1,%2,%3}, [%4];"
                 : "=r"(r[0]), "=r"(r[1]), "=r"(r[2]), "=r"(r[3]) : "r"(addr));
}

__device__ __forceinline__ void mma16816(float* d, const uint32_t* a,
                                         const uint32_t* b) {
    asm volatile(
        "mma.sync.aligned.m16n8k16.row.col.f32.bf16.bf16.f32 "
        "{%0,%1,%2,%3}, {%4,%5,%6,%7}, {%8,%9}, {%0,%1,%2,%3};"
        : "+f"(d[0]), "+f"(d[1]), "+f"(d[2]), "+f"(d[3])
        : "r"(a[0]), "r"(a[1]), "r"(a[2]), "r"(a[3]), "r"(b[0]), "r"(b[1]));
}

// fp32 -> (hi,lo) bf16 pair split, packed as bf16x2 words (element order a,b)
__device__ __forceinline__ void split_pack(float a, float b,
                                           uint32_t& hp, uint32_t& lp) {
    __nv_bfloat16 ha = __float2bfloat16(a);
    __nv_bfloat16 hb = __float2bfloat16(b);
    float la = a - __bfloat162float(ha);   // exact in fp32
    float lb = b - __bfloat162float(hb);
    __nv_bfloat162 hv; hv.x = ha; hv.y = hb;
    __nv_bfloat162 lv = __floats2bfloat162_rn(la, lb);
    hp = *reinterpret_cast<uint32_t*>(&hv);
    lp = *reinterpret_cast<uint32_t*>(&lv);
}

__device__ __forceinline__ float warp_red_max(float v) {
    #pragma unroll
    for (int o = 16; o; o >>= 1)
        v = fmaxf(v, __shfl_xor_sync(0xffffffffu, v, o));
    return v;
}
__device__ __forceinline__ float warp_red_sum(float v) {
    #pragma unroll
    for (int o = 16; o; o >>= 1)
        v += __shfl_xor_sync(0xffffffffu, v, o);
    return v;
}
__device__ __forceinline__ int warp_red_sum_i(int v) {
    #pragma unroll
    for (int o = 16; o; o >>= 1)
        v += __shfl_xor_sync(0xffffffffu, v, o);
    return v;
}

// ---------------------------------------------------------------------------
// Weight prep: W[K,N] fp32 -> hi/lo [N,K] bf16 (transpose + 2-term split).
// ---------------------------------------------------------------------------
__global__ void __launch_bounds__(256)
transpose_split_kernel(const float* __restrict__ W,
                       __nv_bfloat16* __restrict__ Thi,
                       __nv_bfloat16* __restrict__ Tlo,
                       int K, int N)
{
    __shared__ float t[32][33];
    const int n0 = blockIdx.x * 32, k0 = blockIdx.y * 32;
    const int tx = threadIdx.x, ty = threadIdx.y;
    #pragma unroll
    for (int j = ty; j < 32; j += 8)
        t[j][tx] = W[(size_t)(k0 + j) * N + n0 + tx];
    __syncthreads();
    #pragma unroll
    for (int j = ty; j < 32; j += 8) {
        float v = t[tx][j];                       // = W[k0+tx][n0+j]
        __nv_bfloat16 h = __float2bfloat16(v);
        float l = v - __bfloat162float(h);
        size_t o = (size_t)(n0 + j) * K + k0 + tx;
        Thi[o] = h;
        Tlo[o] = __float2bfloat16(l);
    }
}

// ---------------------------------------------------------------------------
// Activation split: fp32 [M,K] -> bf16 hi/lo [M,K].
// ---------------------------------------------------------------------------
__global__ void __launch_bounds__(256)
split_act_kernel(const float4* __restrict__ in, uint2* __restrict__ hi,
                 uint2* __restrict__ lo, int n4)
{
    int i = blockIdx.x * 256 + threadIdx.x;
    if (i < n4) {
        float4 v = in[i];
        uint32_t h0, l0, h1, l1;
        split_pack(v.x, v.y, h0, l0);
        split_pack(v.z, v.w, h1, l1);
        uint2 hh; hh.x = h0; hh.y = h1;
        uint2 ll; ll.x = l0; ll.y = l1;
        hi[i] = hh;
        lo[i] = ll;
    }
}

// ---------------------------------------------------------------------------
// Tensor-core GEMM via mma.sync (bf16, fp32 accum), 3-term split product:
//   C = act( (Ahi+Alo) @ (Bhi+Blo)^T + bias )  ~= AhBh + AhBl + AlBh
// A: [M,K] bf16 hi/lo row-major.  B: [N,K] bf16 hi/lo row-major (pre-transposed).
// CTA tile BM x 128, BK=32, 512 threads / 16 warps (WM x WN grid, warp tile
// 32 x (128/WN)), cp.async 3-stage pipeline, 80B smem row pitch.
// ACT: 0=identity, 1=tanh, 2=relu. OSPLIT: 1 -> write hi/lo bf16, else fp32.
// ---------------------------------------------------------------------------
template<int BM, int ACT, int OSPLIT>
__global__ void __launch_bounds__(512, 1)
mma_gemm(const __nv_bfloat16* __restrict__ Ahi,
         const __nv_bfloat16* __restrict__ Alo,
         const __nv_bfloat16* __restrict__ Bhi,
         const __nv_bfloat16* __restrict__ Blo,
         const float* __restrict__ bias,
         float* __restrict__ Cf,
         __nv_bfloat16* __restrict__ Chi,
         __nv_bfloat16* __restrict__ Clo,
         int M, int N, int K)
{
    constexpr int BK = 32;                     // bf16 elems per chunk
    constexpr int PITCH = 80;                  // bytes per smem row (32*2 + 16 pad)
    constexpr int WM = BM / 32;                // warps along M (4 or 2)
    constexpr int WN = 16 / WM;                // warps along N (4 or 8)
    constexpr int WTN = 128 / WN;              // warp tile N (32 or 16)
    constexpr int NI = WTN / 8;                // n8 tiles per warp (4 or 2)
    constexpr uint32_t OFF_ALO = BM * PITCH;
    constexpr uint32_t OFF_BHI = 2u * BM * PITCH;
    constexpr uint32_t OFF_BLO = OFF_BHI + 128 * PITCH;
    constexpr uint32_t BUFBYTES = OFF_BLO + 128 * PITCH;
    constexpr bool AFULL = (BM * 4 >= 512);    // A loader covers all threads?

    extern __shared__ __align__(128) char smem[];
    const uint32_t sbase = smem_to_u32(smem);

    const int tid    = threadIdx.x;
    const int lane   = tid & 31;
    const int warp   = tid >> 5;
    const int warp_m = warp % WM;
    const int warp_n = warp / WM;
    const int row0   = blockIdx.y * BM;
    const int col0   = blockIdx.x * 128;
    const int nch    = K / BK;

    float acc[2][NI][4];
    #pragma unroll
    for (int mi = 0; mi < 2; mi++)
        #pragma unroll
        for (int ni = 0; ni < NI; ni++)
            #pragma unroll
            for (int r = 0; r < 4; r++) acc[mi][ni][r] = 0.f;

    // ---- chunk loader (cp.async, 16B transfers); commit done by caller ----
    auto load_chunk = [&](int c, int buf) {
        const uint32_t sb = sbase + (uint32_t)buf * BUFBYTES;
        const int kc = c * BK;
        if (AFULL || tid < BM * 4) {
            int m = tid >> 2, seg = tid & 3;
            const __nv_bfloat16* gh = Ahi + (size_t)(row0 + m) * K + kc + seg * 8;
            const __nv_bfloat16* gl = Alo + (size_t)(row0 + m) * K + kc + seg * 8;
            cp16(sb + m * PITCH + seg * 16, gh);
            cp16(sb + OFF_ALO + m * PITCH + seg * 16, gl);
        }
        {
            int n = tid >> 2, seg = tid & 3;   // 512 transfers exactly
            const __nv_bfloat16* gh = Bhi + (size_t)(col0 + n) * K + kc + seg * 8;
            const __nv_bfloat16* gl = Blo + (size_t)(col0 + n) * K + kc + seg * 8;
            cp16(sb + OFF_BHI + n * PITCH + seg * 16, gh);
            cp16(sb + OFF_BLO + n * PITCH + seg * 16, gl);
        }
    };

    // Prologue: chunks 0 and 1 in flight (one commit group each).
    load_chunk(0, 0);
    CP_COMMIT();
    if (nch > 1) load_chunk(1, 1);
    CP_COMMIT();

    const int lm = lane & 15, lq = lane >> 4;         // A ldmatrix lane mapping
    const int bmat = lane >> 3, brow = lane & 7;      // B ldmatrix lane mapping

    for (int c = 0; c < nch; ++c) {
        // Keep two chunks ahead in flight; commit (possibly empty) every iter
        // so the group count stays in lockstep with c.
        if (c + 2 < nch) load_chunk(c + 2, (c + 2) % 3);
        CP_COMMIT();
        CP_WAIT(2);               // groups up to index c complete
        __syncthreads();

        const uint32_t sb = sbase + (uint32_t)(c % 3) * BUFBYTES;
        #pragma unroll
        for (int ks = 0; ks < 2; ks++) {              // two K=16 substeps
            uint32_t aH[2][4], aL[2][4];
            #pragma unroll
            for (int mi = 0; mi < 2; mi++) {
                uint32_t ra = sb +
                    (uint32_t)((warp_m * 32 + mi * 16 + lm) * PITCH +
                               ks * 32 + lq * 16);
                ldsm_x4(aH[mi], ra);
                ldsm_x4(aL[mi], ra + OFF_ALO);
            }
            uint32_t bH[NI][2], bL[NI][2];
            #pragma unroll
            for (int tp = 0; tp < NI / 2; tp++) {
                int t  = tp * 2 + (bmat >> 1);
                int kh = bmat & 1;
                uint32_t rb = sb + OFF_BHI +
                    (uint32_t)((warp_n * WTN + t * 8 + brow) * PITCH +
                               ks * 32 + kh * 16);
                uint32_t q[4];
                ldsm_x4(q, rb);
                bH[tp*2][0] = q[0]; bH[tp*2][1] = q[1];
                bH[tp*2+1][0] = q[2]; bH[tp*2+1][1] = q[3];
                ldsm_x4(q, rb + (OFF_BLO - OFF_BHI));
                bL[tp*2][0] = q[0]; bL[tp*2][1] = q[1];
                bL[tp*2+1][0] = q[2]; bL[tp*2+1][1] = q[3];
            }
            #pragma unroll
            for (int mi = 0; mi < 2; mi++)
                #pragma unroll
                for (int ni = 0; ni < NI; ni++) {
                    mma16816(acc[mi][ni], aH[mi], bH[ni]);
                    mma16816(acc[mi][ni], aH[mi], bL[ni]);
                    mma16816(acc[mi][ni], aL[mi], bH[ni]);
                }
        }
        __syncthreads();          // ldsm reads done before buffer reuse
    }

    // ---- epilogue: bias + activation, fp32 or bf16 hi/lo split output ----
    #pragma unroll
    for (int mi = 0; mi < 2; mi++) {
        #pragma unroll
        for (int ni = 0; ni < NI; ni++) {
            int rbase = row0 + warp_m * 32 + mi * 16 + (lane >> 2);
            int cb    = col0 + warp_n * WTN + ni * 8 + (lane & 3) * 2;
            float b0 = bias[cb], b1 = bias[cb + 1];
            #pragma unroll
            for (int h = 0; h < 2; h++) {
                float v0 = acc[mi][ni][2*h + 0] + b0;
                float v1 = acc[mi][ni][2*h + 1] + b1;
                if (ACT == 1) { v0 = tanhf(v0); v1 = tanhf(v1); }
                if (ACT == 2) { v0 = fmaxf(v0, 0.f); v1 = fmaxf(v1, 0.f); }
                size_t o = (size_t)(rbase + h * 8) * N + cb;
                if (OSPLIT) {
                    uint32_t hp, lp;
                    split_pack(v0, v1, hp, lp);
                    *reinterpret_cast<uint32_t*>(&Chi[o]) = hp;
                    *reinterpret_cast<uint32_t*>(&Clo[o]) = lp;
                } else {
                    float2 ov; ov.x = v0; ov.y = v1;
                    *reinterpret_cast<float2*>(&Cf[o]) = ov;
                }
            }
        }
    }
}

// ---------------------------------------------------------------------------
// Fused sparsemax + gating, one block per row. Warp-shuffle reductions.
// Writes weighted = x * sparsemax(Z) directly as bf16 hi/lo.
// ---------------------------------------------------------------------------
__global__ void __launch_bounds__(256)
sparsemax_gate_kernel(const float* __restrict__ Z, const float* __restrict__ X,
                      __nv_bfloat16* __restrict__ Whi,
                      __nv_bfloat16* __restrict__ Wlo)
{
    __shared__ float z[D_DIM];
    __shared__ float swarp[8];
    __shared__ int   cwarp[8];

    const int tid  = threadIdx.x;
    const int lane = tid & 31;
    const int wid  = tid >> 5;
    const size_t roff = (size_t)blockIdx.x * D_DIM;

    for (int i = tid; i < D_DIM / 4; i += 256)
        reinterpret_cast<float4*>(z)[i] =
            reinterpret_cast<const float4*>(Z + roff)[i];
    __syncthreads();

    float m = -3.402823466e38f;
    for (int i = tid; i < D_DIM; i += 256) m = fmaxf(m, z[i]);
    m = warp_red_max(m);
    if (lane == 0) swarp[wid] = m;
    __syncthreads();
    float tau;
    {
        float m8 = -3.402823466e38f;
        #pragma unroll
        for (int w = 0; w < 8; w++) m8 = fmaxf(m8, swarp[w]);
        tau = m8 - 1.0f;          // f(tau0) >= 0 guaranteed
    }

    for (int it = 0; it < 32; ++it) {
        float s = 0.f; int c = 0;
        for (int i = tid; i < D_DIM; i += 256) {
            float d = z[i] - tau;
            if (d > 0.f) { s += d; c++; }
        }
        s = warp_red_sum(s);
        c = warp_red_sum_i(c);
        __syncthreads();
        if (lane == 0) { swarp[wid] = s; cwarp[wid] = c; }
        __syncthreads();
        float S = 0.f; int C = 0;
        #pragma unroll
        for (int w = 0; w < 8; w++) { S += swarp[w]; C += cwarp[w]; }
        if (C == 0) break;
        float delta = (S - 1.0f) / (float)C;
        tau += delta;
        if (fabsf(delta) <= 1e-7f) break;
    }

    const float* xr = X + roff;
    for (int i = tid; i < D_DIM / 4; i += 256) {
        float4 zv = reinterpret_cast<const float4*>(z)[i];
        float4 xv = reinterpret_cast<const float4*>(xr)[i];
        float w0 = xv.x * fmaxf(zv.x - tau, 0.f);
        float w1 = xv.y * fmaxf(zv.y - tau, 0.f);
        float w2 = xv.z * fmaxf(zv.z - tau, 0.f);
        float w3 = xv.w * fmaxf(zv.w - tau, 0.f);
        uint32_t h0, l0, h1, l1;
        split_pack(w0, w1, h0, l0);
        split_pack(w2, w3, h1, l1);
        uint2 hh; hh.x = h0; hh.y = h1;
        uint2 ll; ll.x = l0; ll.y = l1;
        reinterpret_cast<uint2*>(Whi + roff)[i] = hh;
        reinterpret_cast<uint2*>(Wlo + roff)[i] = ll;
    }
}

// ---------------------------------------------------------------------------
// Final tiny GEMM: out[B,16] = Hh[B,128] @ Wc2[128,16] + bc2.
// ---------------------------------------------------------------------------
__global__ void __launch_bounds__(256)
final_gemm_kernel(const float* __restrict__ Hh, const float* __restrict__ Wc2,
                  const float* __restrict__ bc2, float* __restrict__ out)
{
    __shared__ float sH[16][H_DIM];
    __shared__ float sW[H_DIM][C_DIM];

    const int tid  = threadIdx.x;
    const int row0 = blockIdx.x * 16;

    for (int i = tid; i < 16 * H_DIM / 4; i += 256) {
        int r = i / (H_DIM / 4);
        int c = (i % (H_DIM / 4)) * 4;
        *reinterpret_cast<float4*>(&sH[r][c]) =
            *reinterpret_cast<const float4*>(&Hh[(size_t)(row0 + r) * H_DIM + c]);
    }
    for (int i = tid; i < H_DIM * C_DIM / 4; i += 256) {
        int k = i / (C_DIM / 4);
        int c = (i % (C_DIM / 4)) * 4;
        *reinterpret_cast<float4*>(&sW[k][c]) =
            *reinterpret_cast<const float4*>(&Wc2[k * C_DIM + c]);
    }
    __syncthreads();

    const int r = tid / C_DIM;
    const int c = tid % C_DIM;
    float s = bc2[c];
    #pragma unroll
    for (int k = 0; k < H_DIM; k++) s += sH[r][k] * sW[k][c];
    out[(size_t)(row0 + r) * C_DIM + c] = s;
}

// ---------------------------------------------------------------------------
// Launch sequence (graph-capturable: kernel launches only).
// ---------------------------------------------------------------------------
extern "C" void kernel_launch(void* const* d_in, const int* in_sizes, int n_in,
                              void* d_out, int out_size)
{
    const float* x   = (const float*)d_in[0];
    const float* W1  = (const float*)d_in[1];
    const float* b1  = (const float*)d_in[2];
    const float* W2  = (const float*)d_in[3];
    const float* b2  = (const float*)d_in[4];
    const float* Wc1 = (const float*)d_in[5];
    const float* bc1 = (const float*)d_in[6];
    const float* Wc2 = (const float*)d_in[7];
    const float* bc2 = (const float*)d_in[8];
    float* out = (float*)d_out;
    (void)in_sizes; (void)n_in; (void)out_size;

    float *pA, *pH;
    __nv_bfloat16 *pXh, *pXl, *pTh, *pTl;
    __nv_bfloat16 *pW1h, *pW1l, *pW2h, *pW2l, *pWc1h, *pWc1l;
    cudaGetSymbolAddress((void**)&pA,    g_A);
    cudaGetSymbolAddress((void**)&pH,    g_H);
    cudaGetSymbolAddress((void**)&pXh,   g_Xhi);
    cudaGetSymbolAddress((void**)&pXl,   g_Xlo);
    cudaGetSymbolAddress((void**)&pTh,   g_Thi);
    cudaGetSymbolAddress((void**)&pTl,   g_Tlo);
    cudaGetSymbolAddress((void**)&pW1h,  g_W1t_hi);
    cudaGetSymbolAddress((void**)&pW1l,  g_W1t_lo);
    cudaGetSymbolAddress((void**)&pW2h,  g_W2t_hi);
    cudaGetSymbolAddress((void**)&pW2l,  g_W2t_lo);
    cudaGetSymbolAddress((void**)&pWc1h, g_Wc1t_hi);
    cudaGetSymbolAddress((void**)&pWc1l, g_Wc1t_lo);

    // Dynamic smem: 3 stages * (2*BM + 256) * 80 bytes
    const int SMEM_BM128 = 3 * (2 * 128 + 256) * 80;   // 122880
    const int SMEM_BM64  = 3 * (2 * 64 + 256) * 80;    // 92160
    cudaFuncSetAttribute(mma_gemm<128,1,1>, cudaFuncAttributeMaxDynamicSharedMemorySize, SMEM_BM128);
    cudaFuncSetAttribute(mma_gemm<128,0,0>, cudaFuncAttributeMaxDynamicSharedMemorySize, SMEM_BM128);
    cudaFuncSetAttribute(mma_gemm<64,2,0>,  cudaFuncAttributeMaxDynamicSharedMemorySize, SMEM_BM64);

    // 0) Weight prep: transpose + bf16 hi/lo split.
    transpose_split_kernel<<<dim3(A_DIM / 32, D_DIM / 32), dim3(32, 8)>>>(
        W1, pW1h, pW1l, D_DIM, A_DIM);
    transpose_split_kernel<<<dim3(D_DIM / 32, A_DIM / 32), dim3(32, 8)>>>(
        W2, pW2h, pW2l, A_DIM, D_DIM);
    transpose_split_kernel<<<dim3(H_DIM / 32, D_DIM / 32), dim3(32, 8)>>>(
        Wc1, pWc1h, pWc1l, D_DIM, H_DIM);

    // 0b) Split x -> bf16 hi/lo.
    {
        int n4 = B_ROWS * D_DIM / 4;
        split_act_kernel<<<n4 / 256, 256>>>((const float4*)x, (uint2*)pXh,
                                            (uint2*)pXl, n4);
    }

    // 1) T = tanh(x @ W1 + b1), written as bf16 hi/lo.  [8192,1024], K=4096
    mma_gemm<128,1,1><<<dim3(A_DIM / 128, B_ROWS / 128), 512, SMEM_BM128>>>(
        pXh, pXl, pW1h, pW1l, b1, nullptr, pTh, pTl, B_ROWS, A_DIM, D_DIM);

    // 2) a = T @ W2 + b2 (fp32)          [8192,4096], K=1024
    mma_gemm<128,0,0><<<dim3(D_DIM / 128, B_ROWS / 128), 512, SMEM_BM128>>>(
        pTh, pTl, pW2h, pW2l, b2, pA, nullptr, nullptr, B_ROWS, D_DIM, A_DIM);

    // 3) weighted = x * sparsemax(a), written as bf16 hi/lo into g_X*.
    sparsemax_gate_kernel<<<B_ROWS, 256>>>(pA, x, pXh, pXl);

    // 4) h = relu(weighted @ Wc1 + bc1)  [8192,128], K=4096
    mma_gemm<64,2,0><<<dim3(H_DIM / 128, B_ROWS / 64), 512, SMEM_BM64>>>(
        pXh, pXl, pWc1h, pWc1l, bc1, pH, nullptr, nullptr, B_ROWS, H_DIM, D_DIM);

    // 5) out = h @ Wc2 + bc2             [8192,16], K=128
    final_gemm_kernel<<<B_ROWS / 16, 256>>>(pH, Wc2, bc2, out);
}

// round 11
// speedup vs baseline: 2.0577x; 2.0577x over previous
#include <cuda_runtime.h>
#include <cuda_fp16.h>
#include <cstdint>
#include <math.h>

#define B_ROWS 8192
#define D_DIM  4096
#define A_DIM  1024
#define H_DIM  128
#define C_DIM  16

// ---------------------------------------------------------------------------
// Scratch (module-scope device memory; no runtime allocation).
// ---------------------------------------------------------------------------
__device__ float  g_A[(size_t)B_ROWS * D_DIM];      // 128 MB: attention logits
__device__ float  g_H[B_ROWS * H_DIM];              // 4 MB  : relu(weighted@Wc1+bc1)
__device__ __half g_X[(size_t)B_ROWS * D_DIM];      // 64 MB : fp16(x), then fp16(weighted)
__device__ __half g_T[B_ROWS * A_DIM];              // 16 MB : fp16(tanh(x@W1+b1))
__device__ __half g_W1t_hi[A_DIM * D_DIM];          // [N,K] = [1024,4096]
__device__ __half g_W1t_lo[A_DIM * D_DIM];
__device__ __half g_W2t_hi[D_DIM * A_DIM];          // [4096,1024]
__device__ __half g_W2t_lo[D_DIM * A_DIM];
__device__ __half g_Wc1t_hi[H_DIM * D_DIM];         // [128,4096]
__device__ __half g_Wc1t_lo[H_DIM * D_DIM];

// ---------------------------------------------------------------------------
// PTX helpers — baseline (non-'a') instructions only.
// ---------------------------------------------------------------------------
__device__ __forceinline__ uint32_t smem_to_u32(const void* p) {
    uint32_t a;
    asm("{ .reg .u64 t; cvta.to.shared.u64 t, %1; cvt.u32.u64 %0, t; }"
        : "=r"(a) : "l"(p));
    return a;
}

__device__ __forceinline__ void cp16(uint32_t saddr, const void* gaddr) {
    asm volatile("cp.async.cg.shared.global [%0], [%1], 16;"
                 :: "r"(saddr), "l"(gaddr));
}
#define CP_COMMIT()  asm volatile("cp.async.commit_group;" ::: "memory")
#define CP_WAIT(n)   asm volatile("cp.async.wait_group %0;" :: "n"(n) : "memory")

__device__ __forceinline__ void ldsm_x4(uint32_t* r, uint32_t addr) {
    asm volatile("ldmatrix.sync.aligned.m8n8.x4.shared.b16 {%0,%1,%2,%3}, [%4];"
                 : "=r"(r[0]), "=r"(r[1]), "=r"(r[2]), "=r"(r[3]) : "r"(addr));
}

// m16n8k16 fp16 MMA, fp32 accumulate.
__device__ __forceinline__ void mma16816(float* d, const uint32_t* a,
                                         const uint32_t* b) {
    asm volatile(
        "mma.sync.aligned.m16n8k16.row.col.f32.f16.f16.f32 "
        "{%0,%1,%2,%3}, {%4,%5,%6,%7}, {%8,%9}, {%0,%1,%2,%3};"
        : "+f"(d[0]), "+f"(d[1]), "+f"(d[2]), "+f"(d[3])
        : "r"(a[0]), "r"(a[1]), "r"(a[2]), "r"(a[3]), "r"(b[0]), "r"(b[1]));
}

__device__ __forceinline__ uint32_t pack_h2(float a, float b) {
    __half2 h = __floats2half2_rn(a, b);
    return *reinterpret_cast<uint32_t*>(&h);
}

__device__ __forceinline__ float warp_red_max(float v) {
    #pragma unroll
    for (int o = 16; o; o >>= 1)
        v = fmaxf(v, __shfl_xor_sync(0xffffffffu, v, o));
    return v;
}
__device__ __forceinline__ float warp_red_sum(float v) {
    #pragma unroll
    for (int o = 16; o; o >>= 1)
        v += __shfl_xor_sync(0xffffffffu, v, o);
    return v;
}
__device__ __forceinline__ int warp_red_sum_i(int v) {
    #pragma unroll
    for (int o = 16; o; o >>= 1)
        v += __shfl_xor_sync(0xffffffffu, v, o);
    return v;
}

// ---------------------------------------------------------------------------
// Weight prep: W[K,N] fp32 -> hi/lo [N,K] fp16 (transpose + 2-term split).
// lo lands in fp16 subnormal range for small weights; tensor cores handle it.
// ---------------------------------------------------------------------------
__global__ void __launch_bounds__(256)
transpose_split_kernel(const float* __restrict__ W,
                       __half* __restrict__ Thi,
                       __half* __restrict__ Tlo,
                       int K, int N)
{
    __shared__ float t[32][33];
    const int n0 = blockIdx.x * 32, k0 = blockIdx.y * 32;
    const int tx = threadIdx.x, ty = threadIdx.y;
    #pragma unroll
    for (int j = ty; j < 32; j += 8)
        t[j][tx] = W[(size_t)(k0 + j) * N + n0 + tx];
    __syncthreads();
    #pragma unroll
    for (int j = ty; j < 32; j += 8) {
        float v = t[tx][j];                       // = W[k0+tx][n0+j]
        __half h = __float2half_rn(v);
        float l = v - __half2float(h);
        size_t o = (size_t)(n0 + j) * K + k0 + tx;
        Thi[o] = h;
        Tlo[o] = __float2half_rn(l);
    }
}

// ---------------------------------------------------------------------------
// Activation convert: fp32 [M,K] -> fp16 [M,K] (single term).
// ---------------------------------------------------------------------------
__global__ void __launch_bounds__(256)
tohalf_kernel(const float4* __restrict__ in, uint2* __restrict__ out, int n4)
{
    int i = blockIdx.x * 256 + threadIdx.x;
    if (i < n4) {
        float4 v = in[i];
        uint2 o;
        o.x = pack_h2(v.x, v.y);
        o.y = pack_h2(v.z, v.w);
        out[i] = o;
    }
}

// ---------------------------------------------------------------------------
// Tensor-core GEMM via mma.sync (fp16, fp32 accum), asymmetric 2-term split:
//   C = act( A @ (Bhi+Blo)^T + bias ),  A fp16 (pre-rounded), B fp16 hi/lo.
// A: [M,K] fp16 row-major.  B: [N,K] fp16 hi/lo row-major (pre-transposed).
// CTA tile BM x 128 (BM = MT*32), BK=32, 8 warps (2m x 4n), warp tile MT*16 x 32.
// cp.async 3-stage pipeline, 80B smem row pitch (R8-validated skeleton).
// ACT: 0=identity, 1=tanh, 2=relu. OHALF: 1 -> write fp16, else fp32.
// ---------------------------------------------------------------------------
template<int MT, int ACT, int OHALF>
__global__ void __launch_bounds__(256, 1)
mma_gemm(const __half* __restrict__ A,
         const __half* __restrict__ Bhi,
         const __half* __restrict__ Blo,
         const float* __restrict__ bias,
         float* __restrict__ Cf,
         __half* __restrict__ Ch,
         int M, int N, int K)
{
    constexpr int BM = MT * 32;
    constexpr int BK = 32;                     // fp16 elems per chunk
    constexpr int PITCH = 80;                  // bytes per smem row (32*2 + 16 pad)
    constexpr uint32_t OFF_BHI = (uint32_t)BM * PITCH;
    constexpr uint32_t OFF_BLO = OFF_BHI + 128 * PITCH;
    constexpr uint32_t BUFBYTES = OFF_BLO + 128 * PITCH;
    constexpr int AITER = (BM * 4) / 256;      // 16B transfers per thread (A)
    static_assert((BM * 4) % 256 == 0, "");

    extern __shared__ __align__(128) char smem[];
    const uint32_t sbase = smem_to_u32(smem);

    const int tid    = threadIdx.x;
    const int lane   = tid & 31;
    const int warp   = tid >> 5;
    const int warp_m = warp & 1;               // 2 warps along M
    const int warp_n = warp >> 1;              // 4 warps along N
    const int row0   = blockIdx.y * BM;
    const int col0   = blockIdx.x * 128;
    const int nch    = K / BK;

    float acc[MT][4][4];
    #pragma unroll
    for (int mi = 0; mi < MT; mi++)
        #pragma unroll
        for (int ni = 0; ni < 4; ni++)
            #pragma unroll
            for (int r = 0; r < 4; r++) acc[mi][ni][r] = 0.f;

    // ---- chunk loader (cp.async, 16B transfers); commit done by caller ----
    auto load_chunk = [&](int c, int buf) {
        const uint32_t sb = sbase + (uint32_t)buf * BUFBYTES;
        const int kc = c * BK;
        #pragma unroll
        for (int i = 0; i < AITER; i++) {
            int idx = tid + i * 256;
            int m = idx >> 2, seg = idx & 3;
            const __half* g = A + (size_t)(row0 + m) * K + kc + seg * 8;
            cp16(sb + m * PITCH + seg * 16, g);
        }
        #pragma unroll
        for (int i = 0; i < 2; i++) {
            int idx = tid + i * 256;
            int n = idx >> 2, seg = idx & 3;
            const __half* g = Bhi + (size_t)(col0 + n) * K + kc + seg * 8;
            cp16(sb + OFF_BHI + n * PITCH + seg * 16, g);
        }
        #pragma unroll
        for (int i = 0; i < 2; i++) {
            int idx = tid + i * 256;
            int n = idx >> 2, seg = idx & 3;
            const __half* g = Blo + (size_t)(col0 + n) * K + kc + seg * 8;
            cp16(sb + OFF_BLO + n * PITCH + seg * 16, g);
        }
    };

    // Prologue: chunks 0 and 1 in flight (one commit group each).
    load_chunk(0, 0);
    CP_COMMIT();
    if (nch > 1) load_chunk(1, 1);
    CP_COMMIT();

    const int lm = lane & 15, lq = lane >> 4;         // A ldmatrix lane mapping
    const int bmat = lane >> 3, brow = lane & 7;      // B ldmatrix lane mapping

    for (int c = 0; c < nch; ++c) {
        // Keep two chunks ahead in flight; commit (possibly empty) every iter
        // so the group count stays in lockstep with c.
        if (c + 2 < nch) load_chunk(c + 2, (c + 2) % 3);
        CP_COMMIT();
        CP_WAIT(2);               // groups up to index c complete
        __syncthreads();

        const uint32_t sb = sbase + (uint32_t)(c % 3) * BUFBYTES;
        #pragma unroll
        for (int ks = 0; ks < 2; ks++) {              // two K=16 substeps
            uint32_t aR[MT][4];
            #pragma unroll
            for (int mi = 0; mi < MT; mi++) {
                uint32_t ra = sb +
                    (uint32_t)((warp_m * MT * 16 + mi * 16 + lm) * PITCH +
                               ks * 32 + lq * 16);
                ldsm_x4(aR[mi], ra);
            }
            uint32_t bH[4][2], bL[4][2];
            #pragma unroll
            for (int tp = 0; tp < 2; tp++) {
                int t  = tp * 2 + (bmat >> 1);
                int kh = bmat & 1;
                uint32_t rb = sb + OFF_BHI +
                    (uint32_t)((warp_n * 32 + t * 8 + brow) * PITCH +
                               ks * 32 + kh * 16);
                uint32_t q[4];
                ldsm_x4(q, rb);
                bH[tp*2][0] = q[0]; bH[tp*2][1] = q[1];
                bH[tp*2+1][0] = q[2]; bH[tp*2+1][1] = q[3];
                ldsm_x4(q, rb + (OFF_BLO - OFF_BHI));
                bL[tp*2][0] = q[0]; bL[tp*2][1] = q[1];
                bL[tp*2+1][0] = q[2]; bL[tp*2+1][1] = q[3];
            }
            #pragma unroll
            for (int mi = 0; mi < MT; mi++)
                #pragma unroll
                for (int ni = 0; ni < 4; ni++) {
                    mma16816(acc[mi][ni], aR[mi], bH[ni]);
                    mma16816(acc[mi][ni], aR[mi], bL[ni]);
                }
        }
        __syncthreads();          // ldsm reads done before buffer reuse
    }

    // ---- epilogue: bias + activation, fp32 or fp16 output ----
    #pragma unroll
    for (int mi = 0; mi < MT; mi++) {
        #pragma unroll
        for (int ni = 0; ni < 4; ni++) {
            int rbase = row0 + warp_m * MT * 16 + mi * 16 + (lane >> 2);
            int cb    = col0 + warp_n * 32 + ni * 8 + (lane & 3) * 2;
            float b0 = bias[cb], b1 = bias[cb + 1];
            #pragma unroll
            for (int h = 0; h < 2; h++) {
                float v0 = acc[mi][ni][2*h + 0] + b0;
                float v1 = acc[mi][ni][2*h + 1] + b1;
                if (ACT == 1) { v0 = tanhf(v0); v1 = tanhf(v1); }
                if (ACT == 2) { v0 = fmaxf(v0, 0.f); v1 = fmaxf(v1, 0.f); }
                size_t o = (size_t)(rbase + h * 8) * N + cb;
                if (OHALF) {
                    *reinterpret_cast<uint32_t*>(&Ch[o]) = pack_h2(v0, v1);
                } else {
                    float2 ov; ov.x = v0; ov.y = v1;
                    *reinterpret_cast<float2*>(&Cf[o]) = ov;
                }
            }
        }
    }
}

// ---------------------------------------------------------------------------
// Fused sparsemax + gating, one block per row. Warp-shuffle reductions.
// Writes weighted = x * sparsemax(Z) directly as fp16 (GEMM3 input).
// ---------------------------------------------------------------------------
__global__ void __launch_bounds__(256)
sparsemax_gate_kernel(const float* __restrict__ Z, const float* __restrict__ X,
                      __half* __restrict__ Wh)
{
    __shared__ float z[D_DIM];
    __shared__ float swarp[8];
    __shared__ int   cwarp[8];

    const int tid  = threadIdx.x;
    const int lane = tid & 31;
    const int wid  = tid >> 5;
    const size_t roff = (size_t)blockIdx.x * D_DIM;

    for (int i = tid; i < D_DIM / 4; i += 256)
        reinterpret_cast<float4*>(z)[i] =
            reinterpret_cast<const float4*>(Z + roff)[i];
    __syncthreads();

    float m = -3.402823466e38f;
    for (int i = tid; i < D_DIM; i += 256) m = fmaxf(m, z[i]);
    m = warp_red_max(m);
    if (lane == 0) swarp[wid] = m;
    __syncthreads();
    float tau;
    {
        float m8 = -3.402823466e38f;
        #pragma unroll
        for (int w = 0; w < 8; w++) m8 = fmaxf(m8, swarp[w]);
        tau = m8 - 1.0f;          // f(tau0) >= 0 guaranteed
    }

    for (int it = 0; it < 32; ++it) {
        float s = 0.f; int c = 0;
        for (int i = tid; i < D_DIM; i += 256) {
            float d = z[i] - tau;
            if (d > 0.f) { s += d; c++; }
        }
        s = warp_red_sum(s);
        c = warp_red_sum_i(c);
        __syncthreads();
        if (lane == 0) { swarp[wid] = s; cwarp[wid] = c; }
        __syncthreads();
        float S = 0.f; int C = 0;
        #pragma unroll
        for (int w = 0; w < 8; w++) { S += swarp[w]; C += cwarp[w]; }
        if (C == 0) break;
        float delta = (S - 1.0f) / (float)C;
        tau += delta;
        if (fabsf(delta) <= 1e-7f) break;
    }

    const float* xr = X + roff;
    for (int i = tid; i < D_DIM / 4; i += 256) {
        float4 zv = reinterpret_cast<const float4*>(z)[i];
        float4 xv = reinterpret_cast<const float4*>(xr)[i];
        float w0 = xv.x * fmaxf(zv.x - tau, 0.f);
        float w1 = xv.y * fmaxf(zv.y - tau, 0.f);
        float w2 = xv.z * fmaxf(zv.z - tau, 0.f);
        float w3 = xv.w * fmaxf(zv.w - tau, 0.f);
        uint2 o;
        o.x = pack_h2(w0, w1);
        o.y = pack_h2(w2, w3);
        reinterpret_cast<uint2*>(Wh + roff)[i] = o;
    }
}

// ---------------------------------------------------------------------------
// Final tiny GEMM: out[B,16] = Hh[B,128] @ Wc2[128,16] + bc2.
// ---------------------------------------------------------------------------
__global__ void __launch_bounds__(256)
final_gemm_kernel(const float* __restrict__ Hh, const float* __restrict__ Wc2,
                  const float* __restrict__ bc2, float* __restrict__ out)
{
    __shared__ float sH[16][H_DIM];
    __shared__ float sW[H_DIM][C_DIM];

    const int tid  = threadIdx.x;
    const int row0 = blockIdx.x * 16;

    for (int i = tid; i < 16 * H_DIM / 4; i += 256) {
        int r = i / (H_DIM / 4);
        int c = (i % (H_DIM / 4)) * 4;
        *reinterpret_cast<float4*>(&sH[r][c]) =
            *reinterpret_cast<const float4*>(&Hh[(size_t)(row0 + r) * H_DIM + c]);
    }
    for (int i = tid; i < H_DIM * C_DIM / 4; i += 256) {
        int k = i / (C_DIM / 4);
        int c = (i % (C_DIM / 4)) * 4;
        *reinterpret_cast<float4*>(&sW[k][c]) =
            *reinterpret_cast<const float4*>(&Wc2[k * C_DIM + c]);
    }
    __syncthreads();

    const int r = tid / C_DIM;
    const int c = tid % C_DIM;
    float s = bc2[c];
    #pragma unroll
    for (int k = 0; k < H_DIM; k++) s += sH[r][k] * sW[k][c];
    out[(size_t)(row0 + r) * C_DIM + c] = s;
}

// ---------------------------------------------------------------------------
// Launch sequence (graph-capturable: kernel launches only).
// ---------------------------------------------------------------------------
extern "C" void kernel_launch(void* const* d_in, const int* in_sizes, int n_in,
                              void* d_out, int out_size)
{
    const float* x   = (const float*)d_in[0];
    const float* W1  = (const float*)d_in[1];
    const float* b1  = (const float*)d_in[2];
    const float* W2  = (const float*)d_in[3];
    const float* b2  = (const float*)d_in[4];
    const float* Wc1 = (const float*)d_in[5];
    const float* bc1 = (const float*)d_in[6];
    const float* Wc2 = (const float*)d_in[7];
    const float* bc2 = (const float*)d_in[8];
    float* out = (float*)d_out;
    (void)in_sizes; (void)n_in; (void)out_size;

    float *pA, *pH;
    __half *pX, *pT;
    __half *pW1h, *pW1l, *pW2h, *pW2l, *pWc1h, *pWc1l;
    cudaGetSymbolAddress((void**)&pA,    g_A);
    cudaGetSymbolAddress((void**)&pH,    g_H);
    cudaGetSymbolAddress((void**)&pX,    g_X);
    cudaGetSymbolAddress((void**)&pT,    g_T);
    cudaGetSymbolAddress((void**)&pW1h,  g_W1t_hi);
    cudaGetSymbolAddress((void**)&pW1l,  g_W1t_lo);
    cudaGetSymbolAddress((void**)&pW2h,  g_W2t_hi);
    cudaGetSymbolAddress((void**)&pW2l,  g_W2t_lo);
    cudaGetSymbolAddress((void**)&pWc1h, g_Wc1t_hi);
    cudaGetSymbolAddress((void**)&pWc1l, g_Wc1t_lo);

    // Dynamic smem: 3 stages * (BM + 2*128) * 80 bytes
    const int SMEM_MT4 = 3 * (128 + 256) * 80;   // 92160
    const int SMEM_MT2 = 3 * (64 + 256) * 80;    // 76800
    cudaFuncSetAttribute(mma_gemm<4,1,1>, cudaFuncAttributeMaxDynamicSharedMemorySize, SMEM_MT4);
    cudaFuncSetAttribute(mma_gemm<4,0,0>, cudaFuncAttributeMaxDynamicSharedMemorySize, SMEM_MT4);
    cudaFuncSetAttribute(mma_gemm<2,2,0>, cudaFuncAttributeMaxDynamicSharedMemorySize, SMEM_MT2);

    // 0) Weight prep: transpose + fp16 hi/lo split.
    transpose_split_kernel<<<dim3(A_DIM / 32, D_DIM / 32), dim3(32, 8)>>>(
        W1, pW1h, pW1l, D_DIM, A_DIM);
    transpose_split_kernel<<<dim3(D_DIM / 32, A_DIM / 32), dim3(32, 8)>>>(
        W2, pW2h, pW2l, A_DIM, D_DIM);
    transpose_split_kernel<<<dim3(H_DIM / 32, D_DIM / 32), dim3(32, 8)>>>(
        Wc1, pWc1h, pWc1l, D_DIM, H_DIM);

    // 0b) Convert x -> fp16.
    {
        int n4 = B_ROWS * D_DIM / 4;
        tohalf_kernel<<<n4 / 256, 256>>>((const float4*)x, (uint2*)pX, n4);
    }

    // 1) T = tanh(x @ W1 + b1), written as fp16.  [8192,1024], K=4096
    mma_gemm<4,1,1><<<dim3(A_DIM / 128, B_ROWS / 128), 256, SMEM_MT4>>>(
        pX, pW1h, pW1l, b1, nullptr, pT, B_ROWS, A_DIM, D_DIM);

    // 2) a = T @ W2 + b2 (fp32)          [8192,4096], K=1024
    mma_gemm<4,0,0><<<dim3(D_DIM / 128, B_ROWS / 128), 256, SMEM_MT4>>>(
        pT, pW2h, pW2l, b2, pA, nullptr, B_ROWS, D_DIM, A_DIM);

    // 3) weighted = x * sparsemax(a), written as fp16 into g_X.
    sparsemax_gate_kernel<<<B_ROWS, 256>>>(pA, x, pX);

    // 4) h = relu(weighted @ Wc1 + bc1)  [8192,128], K=4096
    mma_gemm<2,2,0><<<dim3(H_DIM / 128, B_ROWS / 64), 256, SMEM_MT2>>>(
        pX, pWc1h, pWc1l, bc1, pH, nullptr, B_ROWS, H_DIM, D_DIM);

    // 5) out = h @ Wc2 + bc2             [8192,16], K=128
    final_gemm_kernel<<<B_ROWS / 16, 256>>>(pH, Wc2, bc2, out);
}